// round 1
// baseline (speedup 1.0000x reference)
#include <cuda_runtime.h>
#include <cuda_bf16.h>

// S5 SSM forward: L=16384, H=1024, P=512
//   Bu   = bf16round( u_bf @ B_bar_bf^T )           (L, 2P)  GEMM1
//   x    = scan: x_t = a * x_{t-1} + Bu_t           (L, P) complex fp32
//   y    = bf16round(rr) - bf16round(ii) in bf16    (L, H)   GEMM2
//   out  = 2*y + D*u

#define L_   16384
#define H_   1024
#define P_   512
#define N2P  1024          // 2*P
#define NCH  128           // number of scan chunks
#define CT   128           // chunk length (NCH*CT == L_)

// ---------------- device scratch (module-load allocations, allowed) ----------
__device__ __nv_bfloat16 g_ubf[L_ * H_];          // u in bf16
__device__ __nv_bfloat16 g_Bcat[N2P * H_];        // [B_bar_re; B_bar_im], rows = n, K contiguous
__device__ __nv_bfloat16 g_Wcat[H_ * N2P];        // per h: [C_re row ; C_im row]
__device__ __nv_bfloat16 g_Bu[L_ * N2P];          // re cols 0..511, im cols 512..1023
__device__ __nv_bfloat16 g_X [L_ * N2P];          // xre / xim bf16
__device__ float2 g_lam [P_];                      // a = exp(lambda*dt)
__device__ float2 g_coef[P_];                      // (a-1)/lambda
__device__ float2 g_aT  [P_];                      // a^CT
__device__ float2 g_carryE[NCH * P_];
__device__ float2 g_init  [NCH * P_];

// ---------------- prep kernels ----------------------------------------------
__global__ void prep_lam(const float* __restrict__ lre, const float* __restrict__ lim,
                         const float* __restrict__ lstep) {
    int p = threadIdx.x;
    float dt = expf(lstep[p]);
    float lr = lre[p], li = lim[p];
    float er = expf(lr * dt);
    float s, c; sincosf(li * dt, &s, &c);
    float ar = er * c, ai = er * s;
    float nr = ar - 1.0f, ni = ai;
    float den = lr * lr + li * li;
    g_lam[p]  = make_float2(ar, ai);
    g_coef[p] = make_float2((nr * lr + ni * li) / den, (ni * lr - nr * li) / den);
    float xr = ar, xi = ai;
    #pragma unroll
    for (int i = 0; i < 7; i++) { float tr = xr * xr - xi * xi; xi = 2.0f * xr * xi; xr = tr; }
    g_aT[p] = make_float2(xr, xi);   // a^128
}

__global__ void prep_B(const float* __restrict__ Bre, const float* __restrict__ Bim) {
    int idx = blockIdx.x * blockDim.x + threadIdx.x;      // over P_*H_
    int p = idx >> 10;
    float2 cf = g_coef[p];
    float br = Bre[idx], bi = Bim[idx];
    g_Bcat[idx]                 = __float2bfloat16_rn(cf.x * br - cf.y * bi);
    g_Bcat[(P_ << 10) + idx]    = __float2bfloat16_rn(cf.x * bi + cf.y * br);
}

__global__ void prep_W(const float* __restrict__ Cre, const float* __restrict__ Cim) {
    int idx = blockIdx.x * blockDim.x + threadIdx.x;      // over H_*N2P
    int h = idx >> 10, k = idx & 1023;
    float v = (k < P_) ? Cre[h * P_ + k] : Cim[h * P_ + (k - P_)];
    g_Wcat[idx] = __float2bfloat16_rn(v);
}

__global__ void prep_u(const float* __restrict__ u) {
    int i = blockIdx.x * blockDim.x + threadIdx.x;        // over L_*H_/4
    float4 v = reinterpret_cast<const float4*>(u)[i];
    __nv_bfloat162 a, b;
    a.x = __float2bfloat16_rn(v.x); a.y = __float2bfloat16_rn(v.y);
    b.x = __float2bfloat16_rn(v.z); b.y = __float2bfloat16_rn(v.w);
    reinterpret_cast<__nv_bfloat162*>(g_ubf)[2 * i]     = a;
    reinterpret_cast<__nv_bfloat162*>(g_ubf)[2 * i + 1] = b;
}

// ---------------- GEMM (mma.sync m16n8k16 bf16) ------------------------------
__device__ __forceinline__ void mma_bf16(float* d, const unsigned* a, const unsigned* b) {
    asm volatile(
        "mma.sync.aligned.m16n8k16.row.col.f32.bf16.bf16.f32 "
        "{%0,%1,%2,%3}, {%4,%5,%6,%7}, {%8,%9}, {%0,%1,%2,%3};\n"
        : "+f"(d[0]), "+f"(d[1]), "+f"(d[2]), "+f"(d[3])
        : "r"(a[0]), "r"(a[1]), "r"(a[2]), "r"(a[3]), "r"(b[0]), "r"(b[1]));
}

// MODE 0: out = bf16(acc) to outb (GEMM1)
// MODE 1: dual accumulators (kt<16 -> rr, kt>=16 -> ii); epilogue per reference (GEMM2)
template <int MODE>
__global__ __launch_bounds__(256)
void gemm_kernel(const __nv_bfloat16* __restrict__ A,
                 const __nv_bfloat16* __restrict__ Bw,
                 __nv_bfloat16* __restrict__ outb,
                 float* __restrict__ outf,
                 const float* __restrict__ Din,
                 const float* __restrict__ ufp) {
    constexpr int K = 1024, N = 1024;
    constexpr int BM = 128, BN = 64, BK = 32;
    constexpr int KT = K / BK;               // 32
    __shared__ __nv_bfloat16 sA[BM][BK + 8];
    __shared__ __nv_bfloat16 sB[BN][BK + 8];

    int tid = threadIdx.x;
    int lane = tid & 31, wid = tid >> 5;
    int warpM = wid & 3, warpN = wid >> 2;   // 4 x 2 warps, warp tile 32x32
    int gid = lane >> 2, tig = lane & 3;
    int bm = blockIdx.y * BM, bn = blockIdx.x * BN;

    constexpr int NHALF = (MODE == 1) ? 2 : 1;
    float acc[NHALF][2][4][4];
    #pragma unroll
    for (int h = 0; h < NHALF; h++)
        #pragma unroll
        for (int mt = 0; mt < 2; mt++)
            #pragma unroll
            for (int nt = 0; nt < 4; nt++)
                #pragma unroll
                for (int e = 0; e < 4; e++) acc[h][mt][nt][e] = 0.0f;

    int arow = tid >> 2;             // 0..63
    int acol = (tid & 3) * 8;        // 0,8,16,24
    const __nv_bfloat16* Ag = A + (long)(bm + arow) * K + acol;
    const __nv_bfloat16* Bg = Bw + (long)(bn + arow) * K + acol;

    uint4 ra0 = *reinterpret_cast<const uint4*>(Ag);
    uint4 ra1 = *reinterpret_cast<const uint4*>(Ag + 64 * K);
    uint4 rb0 = *reinterpret_cast<const uint4*>(Bg);

    for (int kt = 0; kt < KT; ++kt) {
        *reinterpret_cast<uint4*>(&sA[arow][acol])      = ra0;
        *reinterpret_cast<uint4*>(&sA[arow + 64][acol]) = ra1;
        *reinterpret_cast<uint4*>(&sB[arow][acol])      = rb0;
        __syncthreads();
        if (kt + 1 < KT) {
            ra0 = *reinterpret_cast<const uint4*>(Ag + (kt + 1) * BK);
            ra1 = *reinterpret_cast<const uint4*>(Ag + 64 * K + (kt + 1) * BK);
            rb0 = *reinterpret_cast<const uint4*>(Bg + (kt + 1) * BK);
        }
        const int half = (MODE == 1 && kt >= KT / 2) ? (NHALF - 1) : 0;
        #pragma unroll
        for (int kk = 0; kk < BK; kk += 16) {
            unsigned af[2][4], bfr[4][2];
            int cb = kk + tig * 2;
            #pragma unroll
            for (int mt = 0; mt < 2; ++mt) {
                int r0 = warpM * 32 + mt * 16 + gid;
                af[mt][0] = *reinterpret_cast<const unsigned*>(&sA[r0][cb]);
                af[mt][1] = *reinterpret_cast<const unsigned*>(&sA[r0 + 8][cb]);
                af[mt][2] = *reinterpret_cast<const unsigned*>(&sA[r0][cb + 8]);
                af[mt][3] = *reinterpret_cast<const unsigned*>(&sA[r0 + 8][cb + 8]);
            }
            #pragma unroll
            for (int nt = 0; nt < 4; ++nt) {
                int c0 = warpN * 32 + nt * 8 + gid;
                bfr[nt][0] = *reinterpret_cast<const unsigned*>(&sB[c0][cb]);
                bfr[nt][1] = *reinterpret_cast<const unsigned*>(&sB[c0][cb + 8]);
            }
            #pragma unroll
            for (int mt = 0; mt < 2; ++mt)
                #pragma unroll
                for (int nt = 0; nt < 4; ++nt)
                    mma_bf16(acc[half][mt][nt], af[mt], bfr[nt]);
        }
        __syncthreads();
    }

    // epilogue
    #pragma unroll
    for (int mt = 0; mt < 2; ++mt) {
        #pragma unroll
        for (int nt = 0; nt < 4; ++nt) {
            int row = bm + warpM * 32 + mt * 16 + gid;
            int col = bn + warpN * 32 + nt * 8 + tig * 2;
            if (MODE == 0) {
                __nv_bfloat162 v0, v1;
                v0.x = __float2bfloat16_rn(acc[0][mt][nt][0]);
                v0.y = __float2bfloat16_rn(acc[0][mt][nt][1]);
                v1.x = __float2bfloat16_rn(acc[0][mt][nt][2]);
                v1.y = __float2bfloat16_rn(acc[0][mt][nt][3]);
                *reinterpret_cast<__nv_bfloat162*>(&outb[(long)row * N + col])       = v0;
                *reinterpret_cast<__nv_bfloat162*>(&outb[(long)(row + 8) * N + col]) = v1;
            } else {
                #pragma unroll
                for (int j = 0; j < 2; ++j) {       // j=0 -> row, j=1 -> row+8
                    int r = row + j * 8;
                    float2 o;
                    #pragma unroll
                    for (int e = 0; e < 2; ++e) {
                        float rr = __bfloat162float(__float2bfloat16_rn(acc[0][mt][nt][2 * j + e]));
                        float ii = __bfloat162float(__float2bfloat16_rn(acc[1][mt][nt][2 * j + e]));
                        float y  = __bfloat162float(__float2bfloat16_rn(rr - ii));
                        float ov = 2.0f * y + Din[col + e] * ufp[(long)r * N + col + e];
                        (e == 0 ? o.x : o.y) = ov;
                    }
                    *reinterpret_cast<float2*>(&outf[(long)r * N + col]) = o;
                }
            }
        }
    }
}

// ---------------- blocked scan (constant per-channel decay) ------------------
__global__ void scan_phase1() {
    int p = blockIdx.y * 128 + threadIdx.x;
    int c = blockIdx.x;
    float2 a = g_lam[p];
    float xr = 0.0f, xi = 0.0f;
    long base = (long)c * CT * N2P + p;
    #pragma unroll 4
    for (int t = 0; t < CT; ++t) {
        float br = __bfloat162float(g_Bu[base + (long)t * N2P]);
        float bi = __bfloat162float(g_Bu[base + (long)t * N2P + P_]);
        float nr = a.x * xr - a.y * xi + br;
        float ni = a.x * xi + a.y * xr + bi;
        xr = nr; xi = ni;
    }
    g_carryE[c * P_ + p] = make_float2(xr, xi);
}

__global__ void scan_phase2() {
    int p = threadIdx.x;
    float2 a = g_aT[p];
    float cr = 0.0f, ci = 0.0f;
    for (int c = 0; c < NCH; ++c) {
        g_init[c * P_ + p] = make_float2(cr, ci);
        float2 e = g_carryE[c * P_ + p];
        float nr = a.x * cr - a.y * ci + e.x;
        float ni = a.x * ci + a.y * cr + e.y;
        cr = nr; ci = ni;
    }
}

__global__ void scan_phase3() {
    int p = blockIdx.y * 128 + threadIdx.x;
    int c = blockIdx.x;
    float2 a = g_lam[p];
    float2 x0 = g_init[c * P_ + p];
    float xr = x0.x, xi = x0.y;
    long base = (long)c * CT * N2P + p;
    #pragma unroll 4
    for (int t = 0; t < CT; ++t) {
        float br = __bfloat162float(g_Bu[base + (long)t * N2P]);
        float bi = __bfloat162float(g_Bu[base + (long)t * N2P + P_]);
        float nr = a.x * xr - a.y * xi + br;
        float ni = a.x * xi + a.y * xr + bi;
        xr = nr; xi = ni;
        g_X[base + (long)t * N2P]       = __float2bfloat16_rn(xr);
        g_X[base + (long)t * N2P + P_]  = __float2bfloat16_rn(xi);
    }
}

// ---------------- launch ------------------------------------------------------
extern "C" void kernel_launch(void* const* d_in, const int* in_sizes, int n_in,
                              void* d_out, int out_size) {
    const float* u    = (const float*)d_in[0];
    const float* lre  = (const float*)d_in[1];
    const float* lim  = (const float*)d_in[2];
    const float* Bre  = (const float*)d_in[3];
    const float* Bim  = (const float*)d_in[4];
    const float* Cre  = (const float*)d_in[5];
    const float* Cim  = (const float*)d_in[6];
    const float* Din  = (const float*)d_in[7];
    const float* lstp = (const float*)d_in[8];
    float* out = (float*)d_out;

    __nv_bfloat16 *p_ubf, *p_Bcat, *p_Wcat, *p_Bu, *p_X;
    cudaGetSymbolAddress((void**)&p_ubf,  g_ubf);
    cudaGetSymbolAddress((void**)&p_Bcat, g_Bcat);
    cudaGetSymbolAddress((void**)&p_Wcat, g_Wcat);
    cudaGetSymbolAddress((void**)&p_Bu,   g_Bu);
    cudaGetSymbolAddress((void**)&p_X,    g_X);

    prep_lam<<<1, P_>>>(lre, lim, lstp);
    prep_B<<<(P_ * H_) / 256, 256>>>(Bre, Bim);
    prep_W<<<(H_ * N2P) / 256, 256>>>(Cre, Cim);
    prep_u<<<(L_ * H_ / 4) / 256, 256>>>(u);

    dim3 ggrid(N2P / 64, L_ / 128);
    gemm_kernel<0><<<ggrid, 256>>>(p_ubf, p_Bcat, p_Bu, nullptr, nullptr, nullptr);

    scan_phase1<<<dim3(NCH, P_ / 128), 128>>>();
    scan_phase2<<<1, P_>>>();
    scan_phase3<<<dim3(NCH, P_ / 128), 128>>>();

    gemm_kernel<1><<<ggrid, 256>>>(p_X, p_Wcat, nullptr, out, Din, u);
}

// round 4
// speedup vs baseline: 1.9670x; 1.9670x over previous
#include <cuda_runtime.h>
#include <cuda_bf16.h>
#include <cstdint>

// S5 SSM forward: L=16384, H=1024, P=512 — mma.sync pipelined GEMMs
//   GEMM1: Bu = bf16round( u_bf @ Bcat^T )        (L, 2P)
//   scan : x_t = a * x_{t-1} + Bu_t               (L, P) complex fp32 (blocked)
//   GEMM2: y = bf16(bf16(rr) - bf16(ii))          (L, H), K-split dual accum
//   out  = 2*y + D*u

#define L_   16384
#define H_   1024
#define P_   512
#define N2P  1024
#define NCH  128
#define CT   128

// ---- GEMM tiling ----
#define BM 128
#define BN 64
#define BK 32
#define KITERS 32                  // K=1024 / BK
#define NSTAGE 5
#define ASTRIDE 40                 // BK + 8 pad (80B rows: 16B aligned, conflict-free)
#define A_TILE_BYTES (BM * ASTRIDE * 2)      // 10240
#define B_TILE_BYTES (BN * ASTRIDE * 2)      // 5120
#define STAGE_BYTES  (A_TILE_BYTES + B_TILE_BYTES)  // 15360
#define SMEM_DYN (NSTAGE * STAGE_BYTES)      // 76800

// ---------------- device scratch ---------------------------------------------
__device__ __nv_bfloat16 g_ubf [L_ * H_];
__device__ __nv_bfloat16 g_Bcat[N2P * H_];
__device__ __nv_bfloat16 g_Wcat[H_ * N2P];
__device__ __nv_bfloat16 g_Bu  [L_ * N2P];
__device__ __nv_bfloat16 g_X   [L_ * N2P];
__device__ float2 g_lam[P_], g_coef[P_], g_aT[P_];
__device__ float2 g_carryE[NCH * P_], g_init[NCH * P_];

// ---------------- PTX helpers -------------------------------------------------
__device__ __forceinline__ uint32_t smem_u32(const void* p) {
    uint32_t a;
    asm("{ .reg .u64 t; cvta.to.shared.u64 t, %1; cvt.u32.u64 %0, t; }" : "=r"(a) : "l"(p));
    return a;
}
#define CP_ASYNC16(dst, src) \
    asm volatile("cp.async.cg.shared.global [%0], [%1], 16;\n" :: "r"(dst), "l"(src))
#define CP_COMMIT() asm volatile("cp.async.commit_group;\n" ::: "memory")
#define CP_WAIT(n)  asm volatile("cp.async.wait_group %0;\n" :: "n"(n) : "memory")

__device__ __forceinline__ void ldsm4(uint32_t& r0, uint32_t& r1, uint32_t& r2, uint32_t& r3,
                                      uint32_t addr) {
    asm volatile("ldmatrix.sync.aligned.m8n8.x4.shared.b16 {%0,%1,%2,%3}, [%4];"
                 : "=r"(r0), "=r"(r1), "=r"(r2), "=r"(r3) : "r"(addr));
}
__device__ __forceinline__ void mma_bf16(float* d, const uint32_t* a, const uint32_t* b) {
    asm volatile(
        "mma.sync.aligned.m16n8k16.row.col.f32.bf16.bf16.f32 "
        "{%0,%1,%2,%3}, {%4,%5,%6,%7}, {%8,%9}, {%0,%1,%2,%3};\n"
        : "+f"(d[0]), "+f"(d[1]), "+f"(d[2]), "+f"(d[3])
        : "r"(a[0]), "r"(a[1]), "r"(a[2]), "r"(a[3]), "r"(b[0]), "r"(b[1]));
}
__device__ __forceinline__ float bf16r(float x) {
    return __bfloat162float(__float2bfloat16_rn(x));
}

// ---------------- prep kernels ------------------------------------------------
__global__ void prep_lam(const float* __restrict__ lre, const float* __restrict__ lim,
                         const float* __restrict__ lstep) {
    int p = threadIdx.x;
    float dt = expf(lstep[p]);
    float lr = lre[p], li = lim[p];
    float er = expf(lr * dt);
    float s, c; sincosf(li * dt, &s, &c);
    float ar = er * c, ai = er * s;
    float nr = ar - 1.0f, ni = ai;
    float den = lr * lr + li * li;
    g_lam[p]  = make_float2(ar, ai);
    g_coef[p] = make_float2((nr * lr + ni * li) / den, (ni * lr - nr * li) / den);
    float xr = ar, xi = ai;
    #pragma unroll
    for (int i = 0; i < 7; i++) { float tr = xr*xr - xi*xi; xi = 2.0f*xr*xi; xr = tr; }
    g_aT[p] = make_float2(xr, xi);
}

__global__ void prep_B(const float* __restrict__ Bre, const float* __restrict__ Bim) {
    int idx = blockIdx.x * blockDim.x + threadIdx.x;
    int p = idx >> 10;
    float2 cf = g_coef[p];
    float br = Bre[idx], bi = Bim[idx];
    g_Bcat[idx]              = __float2bfloat16_rn(cf.x * br - cf.y * bi);
    g_Bcat[(P_ << 10) + idx] = __float2bfloat16_rn(cf.x * bi + cf.y * br);
}

__global__ void prep_W(const float* __restrict__ Cre, const float* __restrict__ Cim) {
    int idx = blockIdx.x * blockDim.x + threadIdx.x;
    int h = idx >> 10, k = idx & 1023;
    float v = (k < P_) ? Cre[h * P_ + k] : Cim[h * P_ + (k - P_)];
    g_Wcat[idx] = __float2bfloat16_rn(v);
}

__global__ void prep_u(const float* __restrict__ u) {
    int i = blockIdx.x * blockDim.x + threadIdx.x;
    float4 v = reinterpret_cast<const float4*>(u)[i];
    __nv_bfloat162 a, b;
    a.x = __float2bfloat16_rn(v.x); a.y = __float2bfloat16_rn(v.y);
    b.x = __float2bfloat16_rn(v.z); b.y = __float2bfloat16_rn(v.w);
    reinterpret_cast<__nv_bfloat162*>(g_ubf)[2*i]   = a;
    reinterpret_cast<__nv_bfloat162*>(g_ubf)[2*i+1] = b;
}

// ---------------- GEMM --------------------------------------------------------
__device__ __forceinline__ void fill_stage(uint32_t smbase, int stage,
                                           const __nv_bfloat16* __restrict__ A,
                                           const __nv_bfloat16* __restrict__ Bw,
                                           int bm, int bn, int g, int tid) {
    const uint32_t sbase = smbase + stage * STAGE_BYTES;
    #pragma unroll
    for (int i = 0; i < 3; i++) {
        int task = tid + i * 256;
        if (task < 512) {                          // A: 128 rows x 4 chunks
            int row = task >> 2, ch = task & 3;
            const void* src = A + (long)(bm + row) * 1024 + g * BK + ch * 8;
            CP_ASYNC16(sbase + row * (ASTRIDE * 2) + ch * 16, src);
        } else {                                   // B: 64 rows x 4 chunks
            int t = task - 512;
            int row = t >> 2, ch = t & 3;
            const void* src = Bw + (long)(bn + row) * 1024 + g * BK + ch * 8;
            CP_ASYNC16(sbase + A_TILE_BYTES + row * (ASTRIDE * 2) + ch * 16, src);
        }
    }
}

__device__ __forceinline__ void compute_stage(uint32_t sA, uint32_t sB,
                                              int lane, int warpM, int warpN,
                                              float (&acc)[2][4][4]) {
    #pragma unroll
    for (int kk = 0; kk < BK; kk += 16) {
        uint32_t a[2][4], b[4][2];
        #pragma unroll
        for (int mt = 0; mt < 2; mt++) {
            int row = warpM * 32 + mt * 16 + (lane & 15);
            int col = kk + ((lane >> 4) << 3);
            ldsm4(a[mt][0], a[mt][1], a[mt][2], a[mt][3],
                  sA + (row * ASTRIDE + col) * 2);
        }
        #pragma unroll
        for (int ng = 0; ng < 2; ng++) {
            int rn  = warpN * 32 + ng * 16 + (lane & 7) + ((lane >> 4) << 3);
            int col = kk + (((lane >> 3) & 1) << 3);
            ldsm4(b[2*ng][0], b[2*ng][1], b[2*ng+1][0], b[2*ng+1][1],
                  sB + (rn * ASTRIDE + col) * 2);
        }
        #pragma unroll
        for (int mt = 0; mt < 2; mt++)
            #pragma unroll
            for (int nt = 0; nt < 4; nt++)
                mma_bf16(acc[mt][nt], a[mt], b[nt]);
    }
}

// MODE 0: Bu = bf16(A @ B^T) -> outb
// MODE 1: rr (k-iters 0..15) / ii (16..31); out = 2*bf16(bf16(rr)-bf16(ii)) + D*u
template <int MODE>
__global__ __launch_bounds__(256, 2)
void tc_gemm(const __nv_bfloat16* __restrict__ A, const __nv_bfloat16* __restrict__ Bw,
             __nv_bfloat16* __restrict__ outb, float* __restrict__ outf,
             const float* __restrict__ Din, const float* __restrict__ ufp) {
    extern __shared__ char dsm[];
    const uint32_t smbase = smem_u32(dsm);

    const int tid  = threadIdx.x;
    const int lane = tid & 31;
    const int wid  = tid >> 5;
    const int warpM = wid >> 1, warpN = wid & 1;   // 4 x 2 warps, warp tile 32x32
    const int bm = blockIdx.y * BM, bn = blockIdx.x * BN;

    float acc0[2][4][4], acc1[2][4][4];
    #pragma unroll
    for (int mt = 0; mt < 2; mt++)
        #pragma unroll
        for (int nt = 0; nt < 4; nt++)
            #pragma unroll
            for (int e = 0; e < 4; e++) { acc0[mt][nt][e] = 0.0f; acc1[mt][nt][e] = 0.0f; }

    #pragma unroll
    for (int g = 0; g < NSTAGE - 1; g++) {
        fill_stage(smbase, g, A, Bw, bm, bn, g, tid);
        CP_COMMIT();
    }

    for (int f = 0; f < KITERS; f++) {
        CP_WAIT(NSTAGE - 2);
        __syncthreads();
        const int gnext = f + NSTAGE - 1;
        if (gnext < KITERS)
            fill_stage(smbase, gnext % NSTAGE, A, Bw, bm, bn, gnext, tid);
        CP_COMMIT();

        const uint32_t sA = smbase + (f % NSTAGE) * STAGE_BYTES;
        const uint32_t sB = sA + A_TILE_BYTES;
        if (MODE == 1 && f >= KITERS / 2)
            compute_stage(sA, sB, lane, warpM, warpN, acc1);
        else
            compute_stage(sA, sB, lane, warpM, warpN, acc0);
    }

    // ---------------- epilogue ----------------
    #pragma unroll
    for (int mt = 0; mt < 2; mt++) {
        #pragma unroll
        for (int nt = 0; nt < 4; nt++) {
            const int row0 = bm + warpM * 32 + mt * 16 + (lane >> 2);
            const int col  = bn + warpN * 32 + nt * 8 + (lane & 3) * 2;
            if (MODE == 0) {
                __nv_bfloat162 v0 = __floats2bfloat162_rn(acc0[mt][nt][0], acc0[mt][nt][1]);
                __nv_bfloat162 v1 = __floats2bfloat162_rn(acc0[mt][nt][2], acc0[mt][nt][3]);
                *reinterpret_cast<__nv_bfloat162*>(&outb[(long)row0 * N2P + col])       = v0;
                *reinterpret_cast<__nv_bfloat162*>(&outb[(long)(row0 + 8) * N2P + col]) = v1;
            } else {
                #pragma unroll
                for (int j = 0; j < 2; j++) {          // j=0 -> row0, j=1 -> row0+8
                    const long r = row0 + j * 8;
                    float2 uv = *reinterpret_cast<const float2*>(&ufp[r * H_ + col]);
                    float2 o;
                    #pragma unroll
                    for (int e = 0; e < 2; e++) {
                        float rv = bf16r(acc0[mt][nt][2*j + e]);
                        float iv = bf16r(acc1[mt][nt][2*j + e]);
                        float y  = bf16r(rv - iv);
                        float ue = (e == 0) ? uv.x : uv.y;
                        float ov = 2.0f * y + Din[col + e] * ue;
                        if (e == 0) o.x = ov; else o.y = ov;
                    }
                    *reinterpret_cast<float2*>(&outf[r * H_ + col]) = o;
                }
            }
        }
    }
}

// ---------------- blocked scan ------------------------------------------------
__global__ void scan_phase1() {
    int p = blockIdx.y * 128 + threadIdx.x;
    int c = blockIdx.x;
    float2 a = g_lam[p];
    float xr = 0.0f, xi = 0.0f;
    long base = (long)c * CT * N2P + p;
    #pragma unroll 4
    for (int t = 0; t < CT; ++t) {
        float br = __bfloat162float(g_Bu[base + (long)t * N2P]);
        float bi = __bfloat162float(g_Bu[base + (long)t * N2P + P_]);
        float nr = a.x * xr - a.y * xi + br;
        float ni = a.x * xi + a.y * xr + bi;
        xr = nr; xi = ni;
    }
    g_carryE[c * P_ + p] = make_float2(xr, xi);
}

__global__ void scan_phase2() {
    int p = threadIdx.x;
    float2 a = g_aT[p];
    float cr = 0.0f, ci = 0.0f;
    for (int c = 0; c < NCH; ++c) {
        g_init[c * P_ + p] = make_float2(cr, ci);
        float2 e = g_carryE[c * P_ + p];
        float nr = a.x * cr - a.y * ci + e.x;
        float ni = a.x * ci + a.y * cr + e.y;
        cr = nr; ci = ni;
    }
}

__global__ void scan_phase3() {
    int p = blockIdx.y * 128 + threadIdx.x;
    int c = blockIdx.x;
    float2 a = g_lam[p];
    float2 x0 = g_init[c * P_ + p];
    float xr = x0.x, xi = x0.y;
    long base = (long)c * CT * N2P + p;
    #pragma unroll 4
    for (int t = 0; t < CT; ++t) {
        float br = __bfloat162float(g_Bu[base + (long)t * N2P]);
        float bi = __bfloat162float(g_Bu[base + (long)t * N2P + P_]);
        float nr = a.x * xr - a.y * xi + br;
        float ni = a.x * xi + a.y * xr + bi;
        xr = nr; xi = ni;
        g_X[base + (long)t * N2P]      = __float2bfloat16_rn(xr);
        g_X[base + (long)t * N2P + P_] = __float2bfloat16_rn(xi);
    }
}

// ---------------- launch ------------------------------------------------------
extern "C" void kernel_launch(void* const* d_in, const int* in_sizes, int n_in,
                              void* d_out, int out_size) {
    const float* u    = (const float*)d_in[0];
    const float* lre  = (const float*)d_in[1];
    const float* lim  = (const float*)d_in[2];
    const float* Bre  = (const float*)d_in[3];
    const float* Bim  = (const float*)d_in[4];
    const float* Cre  = (const float*)d_in[5];
    const float* Cim  = (const float*)d_in[6];
    const float* Din  = (const float*)d_in[7];
    const float* lstp = (const float*)d_in[8];
    float* out = (float*)d_out;

    __nv_bfloat16 *p_ubf, *p_Bcat, *p_Wcat, *p_Bu, *p_X;
    cudaGetSymbolAddress((void**)&p_ubf,  g_ubf);
    cudaGetSymbolAddress((void**)&p_Bcat, g_Bcat);
    cudaGetSymbolAddress((void**)&p_Wcat, g_Wcat);
    cudaGetSymbolAddress((void**)&p_Bu,   g_Bu);
    cudaGetSymbolAddress((void**)&p_X,    g_X);

    cudaFuncSetAttribute(tc_gemm<0>, cudaFuncAttributeMaxDynamicSharedMemorySize, SMEM_DYN);
    cudaFuncSetAttribute(tc_gemm<1>, cudaFuncAttributeMaxDynamicSharedMemorySize, SMEM_DYN);

    prep_lam<<<1, P_>>>(lre, lim, lstp);
    prep_B<<<(P_ * H_) / 256, 256>>>(Bre, Bim);
    prep_W<<<(H_ * N2P) / 256, 256>>>(Cre, Cim);
    prep_u<<<(L_ * H_ / 4) / 256, 256>>>(u);

    dim3 ggrid(N2P / BN, L_ / BM);
    tc_gemm<0><<<ggrid, 256, SMEM_DYN>>>(p_ubf, p_Bcat, p_Bu, nullptr, nullptr, nullptr);

    scan_phase1<<<dim3(NCH, P_ / 128), 128>>>();
    scan_phase2<<<1, P_>>>();
    scan_phase3<<<dim3(NCH, P_ / 128), 128>>>();

    tc_gemm<1><<<ggrid, 256, SMEM_DYN>>>(p_X, p_Wcat, nullptr, out, Din, u);
}